// round 13
// baseline (speedup 1.0000x reference)
#include <cuda_runtime.h>
#include <cuda_fp16.h>
#include <cstdint>

#define Nn 8192
#define Mm 128
#define EPSf 1e-4f
#define LDA 136   // fp16 elems per smem tile row (128 + 8 pad)

// ---------------- device scratch (allocation-free) ----------------
static __device__ __half g_S[(size_t)Nn * Nn];    // scores fp16, 128 MB
static __device__ __half g_A16[(size_t)Nn * Mm];  // out2 fp16
static __device__ __half g_B16[(size_t)Nn * Mm];  // out1 fp16
static __device__ float  g_Z[Nn];
static __device__ float  g_W[Nn];
static __device__ float  g_rZ[Nn];
static __device__ float  g_rW[Nn];
static __device__ double g_loss;

__device__ __forceinline__ uint32_t smem_u32(const void* p) {
    uint32_t a;
    asm("{ .reg .u64 t; cvta.to.shared.u64 t, %1; cvt.u32.u64 %0, t; }" : "=r"(a) : "l"(p));
    return a;
}
__device__ __forceinline__ void ldmx4(uint32_t* r, uint32_t addr) {
    asm volatile("ldmatrix.sync.aligned.m8n8.x4.shared.b16 {%0,%1,%2,%3}, [%4];"
                 : "=r"(r[0]), "=r"(r[1]), "=r"(r[2]), "=r"(r[3]) : "r"(addr));
}
// fp16-accumulator MMA
__device__ __forceinline__ void mma16816h(uint32_t& c0, uint32_t& c1,
                                          const uint32_t* a, uint32_t b0, uint32_t b1) {
    asm volatile(
        "mma.sync.aligned.m16n8k16.row.col.f16.f16.f16.f16 "
        "{%0,%1}, {%2,%3,%4,%5}, {%6,%7}, {%0,%1};"
        : "+r"(c0), "+r"(c1)
        : "r"(a[0]), "r"(a[1]), "r"(a[2]), "r"(a[3]), "r"(b0), "r"(b1));
}

__global__ void prep_kernel(const float* __restrict__ out1, const float* __restrict__ out2) {
    int t = blockIdx.x * blockDim.x + threadIdx.x;
    if (t < Nn * Mm / 4) {
        float4 a = *(const float4*)&out2[(size_t)t * 4];
        float4 b = *(const float4*)&out1[(size_t)t * 4];
        __half2 a0 = __float22half2_rn(make_float2(a.x, a.y));
        __half2 a1 = __float22half2_rn(make_float2(a.z, a.w));
        __half2 b0 = __float22half2_rn(make_float2(b.x, b.y));
        __half2 b1 = __float22half2_rn(make_float2(b.z, b.w));
        *(uint2*)&g_A16[(size_t)t * 4] = make_uint2(*(uint32_t*)&a0, *(uint32_t*)&a1);
        *(uint2*)&g_B16[(size_t)t * 4] = make_uint2(*(uint32_t*)&b0, *(uint32_t*)&b1);
    }
    if (t < Nn) { g_Z[t] = 0.0f; g_W[t] = 0.0f; }
    if (t == 0) g_loss = 0.0;
}

#define T_ELEMS (128 * LDA)
#define SMEM_BYTES (2 * T_ELEMS * 2)          // 69632 -> 3 CTAs/SM

__device__ __forceinline__ void load_tiles(__half* At, __half* Bt, int i0, int j0, int tid) {
    #pragma unroll 8
    for (int t = tid; t < 2048; t += 256) {
        int row = t >> 4, q = (t & 15) * 8;
        *(uint4*)&At[row * LDA + q] = *(const uint4*)&g_A16[(size_t)(i0 + row) * Mm + q];
        *(uint4*)&Bt[row * LDA + q] = *(const uint4*)&g_B16[(size_t)(j0 + row) * Mm + q];
    }
}

// MMA body, warp tile 32(m) x 64(n), fp16 accum: ch[2][8][2]
__device__ __forceinline__ void mma_tile_h(uint32_t sA, uint32_t sB, int m0w, int n0w,
                                           int lane, uint32_t ch[2][8][2]) {
    const int aro = (lane & 7) + ((lane >> 3) & 1) * 8;
    const int ako = ((lane >> 4) & 1) * 8;
    const int bro = (lane & 7) + ((lane >> 4) & 1) * 8;
    const int bko = ((lane >> 3) & 1) * 8;
    const uint32_t aoff = (uint32_t)(((m0w + aro) * LDA + ako) * 2);
    uint32_t boff[4];
    #pragma unroll
    for (int p = 0; p < 4; p++)
        boff[p] = (uint32_t)(((n0w + p * 16 + bro) * LDA + bko) * 2);

    #pragma unroll
    for (int kk = 0; kk < 8; kk++) {
        const uint32_t kb = (uint32_t)(kk * 32);
        uint32_t av[2][4], bv[4][4];
        #pragma unroll
        for (int mt = 0; mt < 2; mt++)
            ldmx4(av[mt], sA + aoff + (uint32_t)(mt * 16 * LDA * 2) + kb);
        #pragma unroll
        for (int p = 0; p < 4; p++)
            ldmx4(bv[p], sB + boff[p] + kb);
        #pragma unroll
        for (int mt = 0; mt < 2; mt++)
            #pragma unroll
            for (int nt = 0; nt < 8; nt++) {
                const int p = nt >> 1, r = (nt & 1) * 2;
                mma16816h(ch[mt][nt][0], ch[mt][nt][1], av[mt], bv[p][r], bv[p][r + 1]);
            }
    }
}

// ---------------- Pass 1: GEMM -> direct fragment S store -> sums ----------------
__global__ __launch_bounds__(256, 3) void pass1_sums() {
    extern __shared__ char sm[];
    __half* At = (__half*)sm;
    __half* Bt = At + T_ELEMS;

    const int tid = threadIdx.x, wid = tid >> 5, lane = tid & 31;
    const int i0 = blockIdx.y * 128, j0 = blockIdx.x * 128;
    const int m0w = (wid & 3) * 32, n0w = (wid >> 2) * 64;

    load_tiles(At, Bt, i0, j0, tid);
    __syncthreads();

    uint32_t ch[2][8][2] = {};
    mma_tile_h(smem_u32(At), smem_u32(Bt), m0w, n0w, lane, ch);

    // direct fragment store: quad writes 16B contiguous per row; nt pairs merge
    // into full 32B sectors in L2. Issue first so DRAM drains during sums.
    {
        uint32_t* gS32 = (uint32_t*)g_S;
        const int rbase = i0 + m0w + (lane >> 2);
        const int cbase = j0 + n0w + (lane & 3) * 2;
        #pragma unroll
        for (int mt = 0; mt < 2; mt++) {
            size_t o0 = ((size_t)(rbase + mt * 16) * Nn + cbase) >> 1;
            #pragma unroll
            for (int nt = 0; nt < 8; nt++) {
                gS32[o0 + nt * 4]                = ch[mt][nt][0];
                gS32[o0 + 4 * (Nn / 2) + nt * 4] = ch[mt][nt][1];   // row +8
            }
        }
    }

    // exp + row/col sums from fragments
    float rs[2][2] = {{0.f, 0.f}, {0.f, 0.f}};
    #pragma unroll
    for (int nt = 0; nt < 8; nt++) {
        float2 e00 = __half22float2(*(__half2*)&ch[0][nt][0]);
        float2 e01 = __half22float2(*(__half2*)&ch[0][nt][1]);
        float2 e10 = __half22float2(*(__half2*)&ch[1][nt][0]);
        float2 e11 = __half22float2(*(__half2*)&ch[1][nt][1]);
        e00.x = __expf(e00.x); e00.y = __expf(e00.y);
        e01.x = __expf(e01.x); e01.y = __expf(e01.y);
        e10.x = __expf(e10.x); e10.y = __expf(e10.y);
        e11.x = __expf(e11.x); e11.y = __expf(e11.y);

        rs[0][0] += e00.x + e00.y;  rs[0][1] += e01.x + e01.y;
        rs[1][0] += e10.x + e10.y;  rs[1][1] += e11.x + e11.y;

        float v0 = e00.x + e01.x + e10.x + e11.x;
        float v1 = e00.y + e01.y + e10.y + e11.y;
        v0 += __shfl_xor_sync(0xFFFFFFFF, v0, 4);
        v0 += __shfl_xor_sync(0xFFFFFFFF, v0, 8);
        v0 += __shfl_xor_sync(0xFFFFFFFF, v0, 16);
        v1 += __shfl_xor_sync(0xFFFFFFFF, v1, 4);
        v1 += __shfl_xor_sync(0xFFFFFFFF, v1, 8);
        v1 += __shfl_xor_sync(0xFFFFFFFF, v1, 16);
        if (lane < 4) {
            int col = j0 + n0w + nt * 8 + lane * 2;
            atomicAdd(&g_W[col], v0);
            atomicAdd(&g_W[col + 1], v1);
        }
    }
    #pragma unroll
    for (int mt = 0; mt < 2; mt++) {
        float r0 = rs[mt][0], r1 = rs[mt][1];
        r0 += __shfl_xor_sync(0xFFFFFFFF, r0, 1);
        r0 += __shfl_xor_sync(0xFFFFFFFF, r0, 2);
        r1 += __shfl_xor_sync(0xFFFFFFFF, r1, 1);
        r1 += __shfl_xor_sync(0xFFFFFFFF, r1, 2);
        if ((lane & 3) == 0) {
            atomicAdd(&g_Z[i0 + m0w + mt * 16 + (lane >> 2)], r0);
            atomicAdd(&g_Z[i0 + m0w + mt * 16 + 8 + (lane >> 2)], r1);
        }
    }
}

__global__ void recip_kernel() {
    int i = blockIdx.x * blockDim.x + threadIdx.x;
    if (i < Nn) { g_rZ[i] = 1.0f / g_Z[i]; g_rW[i] = 1.0f / g_W[i]; }
}

// ---------------- Pass 2: reversed stream (L2-hot tail first), fused loss ----------------
__global__ __launch_bounds__(256) void pass2_kernel(const float* __restrict__ label) {
    __shared__ float sred[256];
    const size_t nq = (size_t)Nn * Nn / 8;
    const size_t stride = (size_t)gridDim.x * blockDim.x;
    float acc = 0.f;
    for (size_t q = (size_t)blockIdx.x * blockDim.x + threadIdx.x; q < nq; q += stride) {
        size_t base = (nq - 1 - q) * 8;        // reversed: read hot tail of S first
        int i = (int)(base >> 13);
        int j = (int)(base & (Nn - 1));
        uint4 sv = *(const uint4*)((const uint32_t*)g_S + (base >> 1));
        float4 l0 = *(const float4*)(label + base);
        float4 l1 = *(const float4*)(label + base + 4);
        float  rZ = g_rZ[i];
        float4 w0 = *(const float4*)&g_rW[j];
        float4 w1 = *(const float4*)&g_rW[j + 4];

        float2 s0 = __half22float2(*(__half2*)&sv.x);
        float2 s1 = __half22float2(*(__half2*)&sv.y);
        float2 s2 = __half22float2(*(__half2*)&sv.z);
        float2 s3 = __half22float2(*(__half2*)&sv.w);

        float e0 = __expf(s0.x), e1 = __expf(s0.y), e2 = __expf(s1.x), e3 = __expf(s1.y);
        float e4 = __expf(s2.x), e5 = __expf(s2.y), e6 = __expf(s3.x), e7 = __expf(s3.y);

        acc += l0.x * __logf(fmaf(e0, rZ, EPSf) * fmaf(e0, w0.x, EPSf));
        acc += l0.y * __logf(fmaf(e1, rZ, EPSf) * fmaf(e1, w0.y, EPSf));
        acc += l0.z * __logf(fmaf(e2, rZ, EPSf) * fmaf(e2, w0.z, EPSf));
        acc += l0.w * __logf(fmaf(e3, rZ, EPSf) * fmaf(e3, w0.w, EPSf));
        acc += l1.x * __logf(fmaf(e4, rZ, EPSf) * fmaf(e4, w1.x, EPSf));
        acc += l1.y * __logf(fmaf(e5, rZ, EPSf) * fmaf(e5, w1.y, EPSf));
        acc += l1.z * __logf(fmaf(e6, rZ, EPSf) * fmaf(e6, w1.z, EPSf));
        acc += l1.w * __logf(fmaf(e7, rZ, EPSf) * fmaf(e7, w1.w, EPSf));
    }
    sred[threadIdx.x] = acc;
    __syncthreads();
    #pragma unroll
    for (int s = 128; s > 0; s >>= 1) {
        if (threadIdx.x < s) sred[threadIdx.x] += sred[threadIdx.x + s];
        __syncthreads();
    }
    if (threadIdx.x == 0) atomicAdd(&g_loss, -(double)sred[0]);
}

__global__ void final_kernel(float* out) { out[0] = (float)g_loss; }

extern "C" void kernel_launch(void* const* d_in, const int* in_sizes, int n_in,
                              void* d_out, int out_size) {
    const float* out1  = (const float*)d_in[0];
    const float* out2  = (const float*)d_in[1];
    const float* label = (const float*)d_in[2];

    cudaFuncSetAttribute(pass1_sums, cudaFuncAttributeMaxDynamicSharedMemorySize, SMEM_BYTES);

    prep_kernel<<<(Nn * Mm / 4 + 255) / 256, 256>>>(out1, out2);
    dim3 grid(Nn / 128, Nn / 128);
    pass1_sums<<<grid, 256, SMEM_BYTES>>>();
    recip_kernel<<<32, 256>>>();
    pass2_kernel<<<8192, 256>>>(label);
    final_kernel<<<1, 1>>>((float*)d_out);
}

// round 14
// speedup vs baseline: 1.1606x; 1.1606x over previous
#include <cuda_runtime.h>
#include <cuda_fp16.h>
#include <cstdint>

#define Nn 8192
#define Mm 128
#define EPSf 1e-4f
#define LDA 136      // fp16 elems per smem tile row (128 + 8 pad)
#define SQ 1.5f      // int8 score scale
#define SQI (1.0f / 1.5f)
#define LDS8 144     // bytes per staged int8 row (128 + 16 pad)

// ---------------- device scratch (allocation-free) ----------------
static __device__ int8_t g_S8[(size_t)Nn * Nn];   // scores int8, 64 MB
static __device__ __half g_A16[(size_t)Nn * Mm];
static __device__ __half g_B16[(size_t)Nn * Mm];
static __device__ float  g_Z[Nn];
static __device__ float  g_W[Nn];
static __device__ float  g_rZ[Nn];
static __device__ float  g_rW[Nn];
static __device__ double g_loss;

__device__ __forceinline__ uint32_t smem_u32(const void* p) {
    uint32_t a;
    asm("{ .reg .u64 t; cvta.to.shared.u64 t, %1; cvt.u32.u64 %0, t; }" : "=r"(a) : "l"(p));
    return a;
}
__device__ __forceinline__ void ldmx4(uint32_t* r, uint32_t addr) {
    asm volatile("ldmatrix.sync.aligned.m8n8.x4.shared.b16 {%0,%1,%2,%3}, [%4];"
                 : "=r"(r[0]), "=r"(r[1]), "=r"(r[2]), "=r"(r[3]) : "r"(addr));
}
__device__ __forceinline__ void mma16816h(uint32_t& c0, uint32_t& c1,
                                          const uint32_t* a, uint32_t b0, uint32_t b1) {
    asm volatile(
        "mma.sync.aligned.m16n8k16.row.col.f16.f16.f16.f16 "
        "{%0,%1}, {%2,%3,%4,%5}, {%6,%7}, {%0,%1};"
        : "+r"(c0), "+r"(c1)
        : "r"(a[0]), "r"(a[1]), "r"(a[2]), "r"(a[3]), "r"(b0), "r"(b1));
}

__global__ void prep_kernel(const float* __restrict__ out1, const float* __restrict__ out2) {
    int t = blockIdx.x * blockDim.x + threadIdx.x;
    if (t < Nn * Mm / 4) {
        float4 a = *(const float4*)&out2[(size_t)t * 4];
        float4 b = *(const float4*)&out1[(size_t)t * 4];
        __half2 a0 = __float22half2_rn(make_float2(a.x, a.y));
        __half2 a1 = __float22half2_rn(make_float2(a.z, a.w));
        __half2 b0 = __float22half2_rn(make_float2(b.x, b.y));
        __half2 b1 = __float22half2_rn(make_float2(b.z, b.w));
        *(uint2*)&g_A16[(size_t)t * 4] = make_uint2(*(uint32_t*)&a0, *(uint32_t*)&a1);
        *(uint2*)&g_B16[(size_t)t * 4] = make_uint2(*(uint32_t*)&b0, *(uint32_t*)&b1);
    }
    if (t < Nn) { g_Z[t] = 0.0f; g_W[t] = 0.0f; }
    if (t == 0) g_loss = 0.0;
}

#define T_ELEMS (128 * LDA)
#define SMEM_BYTES (2 * T_ELEMS * 2)          // 69632 -> 3 CTAs/SM

__device__ __forceinline__ void load_tiles(__half* At, __half* Bt, int i0, int j0, int tid) {
    #pragma unroll 8
    for (int t = tid; t < 2048; t += 256) {
        int row = t >> 4, q = (t & 15) * 8;
        *(uint4*)&At[row * LDA + q] = *(const uint4*)&g_A16[(size_t)(i0 + row) * Mm + q];
        *(uint4*)&Bt[row * LDA + q] = *(const uint4*)&g_B16[(size_t)(j0 + row) * Mm + q];
    }
}

// MMA body, warp tile 32(m) x 64(n), fp16 accum: ch[2][8][2]
__device__ __forceinline__ void mma_tile_h(uint32_t sA, uint32_t sB, int m0w, int n0w,
                                           int lane, uint32_t ch[2][8][2]) {
    const int aro = (lane & 7) + ((lane >> 3) & 1) * 8;
    const int ako = ((lane >> 4) & 1) * 8;
    const int bro = (lane & 7) + ((lane >> 4) & 1) * 8;
    const int bko = ((lane >> 3) & 1) * 8;
    const uint32_t aoff = (uint32_t)(((m0w + aro) * LDA + ako) * 2);
    uint32_t boff[4];
    #pragma unroll
    for (int p = 0; p < 4; p++)
        boff[p] = (uint32_t)(((n0w + p * 16 + bro) * LDA + bko) * 2);

    #pragma unroll
    for (int kk = 0; kk < 8; kk++) {
        const uint32_t kb = (uint32_t)(kk * 32);
        uint32_t av[2][4], bv[4][4];
        #pragma unroll
        for (int mt = 0; mt < 2; mt++)
            ldmx4(av[mt], sA + aoff + (uint32_t)(mt * 16 * LDA * 2) + kb);
        #pragma unroll
        for (int p = 0; p < 4; p++)
            ldmx4(bv[p], sB + boff[p] + kb);
        #pragma unroll
        for (int mt = 0; mt < 2; mt++)
            #pragma unroll
            for (int nt = 0; nt < 8; nt++) {
                const int p = nt >> 1, r = (nt & 1) * 2;
                mma16816h(ch[mt][nt][0], ch[mt][nt][1], av[mt], bv[p][r], bv[p][r + 1]);
            }
    }
}

__device__ __forceinline__ int8_t q8(float f) {
    float v = fminf(fmaxf(f * SQ, -120.f), 120.f);
    return (int8_t)__float2int_rn(v);
}

// ---------------- Pass 1: GEMM -> sums + int8 staged S store ----------------
__global__ __launch_bounds__(256, 3) void pass1_sums() {
    extern __shared__ char sm[];
    __half* At = (__half*)sm;
    __half* Bt = At + T_ELEMS;
    int8_t* stage = (int8_t*)sm;   // overlays A tile after MMA (128 x 144 B = 18432 B)

    const int tid = threadIdx.x, wid = tid >> 5, lane = tid & 31;
    const int i0 = blockIdx.y * 128, j0 = blockIdx.x * 128;
    const int m0w = (wid & 3) * 32, n0w = (wid >> 2) * 64;

    load_tiles(At, Bt, i0, j0, tid);
    __syncthreads();

    uint32_t ch[2][8][2] = {};
    mma_tile_h(smem_u32(At), smem_u32(Bt), m0w, n0w, lane, ch);

    __syncthreads();   // tiles dead; stage region reusable

    // exp + sums + int8 quantize-stage, all from fragments
    float rs[2][2] = {{0.f, 0.f}, {0.f, 0.f}};
    const int rq = lane >> 2;
    const int cq = n0w + (lane & 3) * 2;
    #pragma unroll
    for (int nt = 0; nt < 8; nt++) {
        float2 f00 = __half22float2(*(__half2*)&ch[0][nt][0]);
        float2 f01 = __half22float2(*(__half2*)&ch[0][nt][1]);
        float2 f10 = __half22float2(*(__half2*)&ch[1][nt][0]);
        float2 f11 = __half22float2(*(__half2*)&ch[1][nt][1]);

        // stage int8 pairs
        const int col = cq + nt * 8;
        *(char2*)&stage[(size_t)(m0w + rq)      * LDS8 + col] = make_char2(q8(f00.x), q8(f00.y));
        *(char2*)&stage[(size_t)(m0w + rq + 8)  * LDS8 + col] = make_char2(q8(f01.x), q8(f01.y));
        *(char2*)&stage[(size_t)(m0w + rq + 16) * LDS8 + col] = make_char2(q8(f10.x), q8(f10.y));
        *(char2*)&stage[(size_t)(m0w + rq + 24) * LDS8 + col] = make_char2(q8(f11.x), q8(f11.y));

        float e00x = __expf(f00.x), e00y = __expf(f00.y);
        float e01x = __expf(f01.x), e01y = __expf(f01.y);
        float e10x = __expf(f10.x), e10y = __expf(f10.y);
        float e11x = __expf(f11.x), e11y = __expf(f11.y);

        rs[0][0] += e00x + e00y;  rs[0][1] += e01x + e01y;
        rs[1][0] += e10x + e10y;  rs[1][1] += e11x + e11y;

        float v0 = e00x + e01x + e10x + e11x;
        float v1 = e00y + e01y + e10y + e11y;
        v0 += __shfl_xor_sync(0xFFFFFFFF, v0, 4);
        v0 += __shfl_xor_sync(0xFFFFFFFF, v0, 8);
        v0 += __shfl_xor_sync(0xFFFFFFFF, v0, 16);
        v1 += __shfl_xor_sync(0xFFFFFFFF, v1, 4);
        v1 += __shfl_xor_sync(0xFFFFFFFF, v1, 8);
        v1 += __shfl_xor_sync(0xFFFFFFFF, v1, 16);
        if (lane < 4) {
            int col2 = j0 + n0w + nt * 8 + lane * 2;
            atomicAdd(&g_W[col2], v0);
            atomicAdd(&g_W[col2 + 1], v1);
        }
    }
    #pragma unroll
    for (int mt = 0; mt < 2; mt++) {
        float r0 = rs[mt][0], r1 = rs[mt][1];
        r0 += __shfl_xor_sync(0xFFFFFFFF, r0, 1);
        r0 += __shfl_xor_sync(0xFFFFFFFF, r0, 2);
        r1 += __shfl_xor_sync(0xFFFFFFFF, r1, 1);
        r1 += __shfl_xor_sync(0xFFFFFFFF, r1, 2);
        if ((lane & 3) == 0) {
            atomicAdd(&g_Z[i0 + m0w + mt * 16 + rq], r0);
            atomicAdd(&g_Z[i0 + m0w + mt * 16 + 8 + rq], r1);
        }
    }
    __syncthreads();

    // coalesced int8 S store: warp does 16 rows, 4 rows/iter, 16 B per lane
    #pragma unroll
    for (int it = 0; it < 4; it++) {
        int r = wid * 16 + it * 4 + (lane >> 3);
        int c16 = (lane & 7) * 16;
        uint4 v = *(const uint4*)&stage[(size_t)r * LDS8 + c16];
        *(uint4*)&g_S8[(size_t)(i0 + r) * Nn + j0 + c16] = v;
    }
}

__global__ void recip_kernel() {
    int i = blockIdx.x * blockDim.x + threadIdx.x;
    if (i < Nn) { g_rZ[i] = 1.0f / g_Z[i]; g_rW[i] = 1.0f / g_W[i]; }
}

// ---------------- Pass 2: pure stream of int8 S + fp32 label, fused loss ----------------
__global__ __launch_bounds__(256) void pass2_kernel(const float* __restrict__ label) {
    __shared__ float sred[256];
    const size_t nq = (size_t)Nn * Nn / 8;
    const size_t stride = (size_t)gridDim.x * blockDim.x;
    float acc = 0.f;
    for (size_t q = (size_t)blockIdx.x * blockDim.x + threadIdx.x; q < nq; q += stride) {
        size_t base = q * 8;
        int i = (int)(base >> 13);
        int j = (int)(base & (Nn - 1));
        uint2 sv = *(const uint2*)(g_S8 + base);
        float4 l0 = *(const float4*)(label + base);
        float4 l1 = *(const float4*)(label + base + 4);
        float  rZ = g_rZ[i];
        float4 w0 = *(const float4*)&g_rW[j];
        float4 w1 = *(const float4*)&g_rW[j + 4];

        float e0 = __expf(SQI * (float)(int)(int8_t)(sv.x));
        float e1 = __expf(SQI * (float)(int)(int8_t)(sv.x >> 8));
        float e2 = __expf(SQI * (float)(int)(int8_t)(sv.x >> 16));
        float e3 = __expf(SQI * (float)(int)(int8_t)(sv.x >> 24));
        float e4 = __expf(SQI * (float)(int)(int8_t)(sv.y));
        float e5 = __expf(SQI * (float)(int)(int8_t)(sv.y >> 8));
        float e6 = __expf(SQI * (float)(int)(int8_t)(sv.y >> 16));
        float e7 = __expf(SQI * (float)(int)(int8_t)(sv.y >> 24));

        acc += l0.x * __logf(fmaf(e0, rZ, EPSf) * fmaf(e0, w0.x, EPSf));
        acc += l0.y * __logf(fmaf(e1, rZ, EPSf) * fmaf(e1, w0.y, EPSf));
        acc += l0.z * __logf(fmaf(e2, rZ, EPSf) * fmaf(e2, w0.z, EPSf));
        acc += l0.w * __logf(fmaf(e3, rZ, EPSf) * fmaf(e3, w0.w, EPSf));
        acc += l1.x * __logf(fmaf(e4, rZ, EPSf) * fmaf(e4, w1.x, EPSf));
        acc += l1.y * __logf(fmaf(e5, rZ, EPSf) * fmaf(e5, w1.y, EPSf));
        acc += l1.z * __logf(fmaf(e6, rZ, EPSf) * fmaf(e6, w1.z, EPSf));
        acc += l1.w * __logf(fmaf(e7, rZ, EPSf) * fmaf(e7, w1.w, EPSf));
    }
    sred[threadIdx.x] = acc;
    __syncthreads();
    #pragma unroll
    for (int s = 128; s > 0; s >>= 1) {
        if (threadIdx.x < s) sred[threadIdx.x] += sred[threadIdx.x + s];
        __syncthreads();
    }
    if (threadIdx.x == 0) atomicAdd(&g_loss, -(double)sred[0]);
}

__global__ void final_kernel(float* out) { out[0] = (float)g_loss; }

extern "C" void kernel_launch(void* const* d_in, const int* in_sizes, int n_in,
                              void* d_out, int out_size) {
    const float* out1  = (const float*)d_in[0];
    const float* out2  = (const float*)d_in[1];
    const float* label = (const float*)d_in[2];

    cudaFuncSetAttribute(pass1_sums, cudaFuncAttributeMaxDynamicSharedMemorySize, SMEM_BYTES);

    prep_kernel<<<(Nn * Mm / 4 + 255) / 256, 256>>>(out1, out2);
    dim3 grid(Nn / 128, Nn / 128);
    pass1_sums<<<grid, 256, SMEM_BYTES>>>();
    recip_kernel<<<32, 256>>>();
    pass2_kernel<<<8192, 256>>>(label);
    final_kernel<<<1, 1>>>((float*)d_out);
}